// round 16
// baseline (speedup 1.0000x reference)
#include <cuda_runtime.h>
#include <math.h>
#include <stdint.h>

#define D_MODEL 1024
#define D_FF    4096
#define NE      8
#define CAP     4096
#define BK      64          // halves per K-tile

// ---------------- device scratch ----------------
__device__ __align__(64) unsigned g_ctrl[16];   // [0..7] counts, [8..15] sumprobs
__device__ int      g_tokidx[NE * CAP];
__device__ float    g_tokw[NE * CAP];
__device__ unsigned g_xh[(size_t)CAP * D_MODEL / 2];
__device__ unsigned g_w1h[(size_t)NE * D_MODEL * D_FF / 2];
__device__ unsigned g_w2h[(size_t)NE * D_FF * D_MODEL / 2];
__device__ unsigned g_hh[(size_t)NE * CAP * D_FF / 2];

#define G_COUNTS   ((int*)g_ctrl)
#define G_SUMPROBS (((float*)g_ctrl) + 8)

// ---------------- helpers ----------------
__device__ __forceinline__ unsigned pack_h2(float lo, float hi) {
    unsigned u;
    asm("cvt.rn.f16x2.f32 %0, %1, %2;" : "=r"(u) : "f"(hi), "f"(lo));
    return u;
}

__device__ __forceinline__ uint32_t smem_u32(const void* p) {
    uint32_t a;
    asm("{ .reg .u64 t; cvta.to.shared.u64 t, %1; cvt.u32.u64 %0, t; }" : "=r"(a) : "l"(p));
    return a;
}

__device__ __forceinline__ void mma_f16(float c[4],
                                        unsigned a0, unsigned a1, unsigned a2, unsigned a3,
                                        unsigned b0, unsigned b1) {
    asm volatile(
        "mma.sync.aligned.m16n8k16.row.col.f32.f16.f16.f32 "
        "{%0,%1,%2,%3}, {%4,%5,%6,%7}, {%8,%9}, {%0,%1,%2,%3};\n"
        : "+f"(c[0]), "+f"(c[1]), "+f"(c[2]), "+f"(c[3])
        : "r"(a0), "r"(a1), "r"(a2), "r"(a3), "r"(b0), "r"(b1));
}

#define LDMX4(r0, r1, r2, r3, addr) \
    asm volatile("ldmatrix.sync.aligned.m8n8.x4.shared.b16 {%0,%1,%2,%3}, [%4];" \
        : "=r"(r0), "=r"(r1), "=r"(r2), "=r"(r3) : "r"(addr))

#define LDMX4T(r0, r1, r2, r3, addr) \
    asm volatile("ldmatrix.sync.aligned.m8n8.x4.trans.shared.b16 {%0,%1,%2,%3}, [%4];" \
        : "=r"(r0), "=r"(r1), "=r"(r2), "=r"(r3) : "r"(addr))

__device__ __forceinline__ void cp16(uint32_t dst, const void* src) {
    asm volatile("cp.async.cg.shared.global [%0], [%1], 16;" :: "r"(dst), "l"(src));
}
#define CP_COMMIT() asm volatile("cp.async.commit_group;" ::: "memory")
#define CP_WAIT0()  asm volatile("cp.async.wait_group 0;" ::: "memory")

// smem geometry (bytes): ctrl 1KB | A0 | A1 | B0 | B1
#define APITCH 144
#define BPITCH 272
#define ABYTES (128 * APITCH)
#define BBYTES (BK * BPITCH)
#define OFFA(b) (1024 + (b) * ABYTES)
#define OFFB(b) (1024 + 2 * ABYTES + (b) * BBYTES)
#define DYN_BYTES (1024 + 2 * ABYTES + 2 * BBYTES)   // 72704

// 8-float wide convert: 2x LDG.128 -> 1x STG.128
__device__ __forceinline__ void conv8(const float* __restrict__ src,
                                      unsigned* __restrict__ dst, size_t j8) {
    float4 v0 = ((const float4*)src)[j8 * 2];
    float4 v1 = ((const float4*)src)[j8 * 2 + 1];
    uint4 o;
    o.x = pack_h2(v0.x, v0.y); o.y = pack_h2(v0.z, v0.w);
    o.z = pack_h2(v1.x, v1.y); o.w = pack_h2(v1.z, v1.w);
    ((uint4*)dst)[j8] = o;
}

// ---------------- merged router + fp16 conversion of w1|x (no smem) ----------------
__global__ void conv_router_kernel(const float* __restrict__ x,
                                   const float* __restrict__ rw,
                                   const float* __restrict__ rb,
                                   const float* __restrict__ w1,
                                   float* __restrict__ out,
                                   int T, int nRouterBlocks,
                                   size_t n8x, size_t n8w) {
    if (blockIdx.x < (unsigned)nRouterBlocks) {
        int warp = threadIdx.x >> 5;
        int lane = threadIdx.x & 31;
        int tok = blockIdx.x * 8 + warp;
        if (tok >= T) return;

        {   // zero this token's output row
            float4* orow = (float4*)(out + (size_t)tok * D_MODEL);
            float4 z = make_float4(0.f, 0.f, 0.f, 0.f);
#pragma unroll
            for (int i = 0; i < D_MODEL / 4 / 32; i++)
                orow[lane + i * 32] = z;
        }

        const float* xr = x + (size_t)tok * D_MODEL;
        float acc[NE];
#pragma unroll
        for (int e = 0; e < NE; e++) acc[e] = 0.0f;
        for (int k = lane; k < D_MODEL; k += 32) {
            float xv = xr[k];
            float4 r0 = __ldg((const float4*)(rw + (size_t)k * NE));
            float4 r1 = __ldg((const float4*)(rw + (size_t)k * NE + 4));
            acc[0] += xv * r0.x; acc[1] += xv * r0.y;
            acc[2] += xv * r0.z; acc[3] += xv * r0.w;
            acc[4] += xv * r1.x; acc[5] += xv * r1.y;
            acc[6] += xv * r1.z; acc[7] += xv * r1.w;
        }
#pragma unroll
        for (int e = 0; e < NE; e++) {
#pragma unroll
            for (int off = 16; off > 0; off >>= 1)
                acc[e] += __shfl_xor_sync(0xFFFFFFFFu, acc[e], off);
        }

        if (lane == 0) {
            float logit[NE]; float m = -1e30f;
#pragma unroll
            for (int e = 0; e < NE; e++) { logit[e] = acc[e] + rb[e]; m = fmaxf(m, logit[e]); }
            float p[NE]; float s = 0.0f;
#pragma unroll
            for (int e = 0; e < NE; e++) { p[e] = __expf(logit[e] - m); s += p[e]; }
            float inv = 1.0f / s;
#pragma unroll
            for (int e = 0; e < NE; e++) p[e] *= inv;
#pragma unroll
            for (int e = 0; e < NE; e++) atomicAdd(&G_SUMPROBS[e], p[e]);

            int i1 = 0; float v1 = p[0];
#pragma unroll
            for (int e = 1; e < NE; e++) if (p[e] > v1) { v1 = p[e]; i1 = e; }
            int i2 = -1; float v2 = -1.0f;
#pragma unroll
            for (int e = 0; e < NE; e++) if (e != i1 && p[e] > v2) { v2 = p[e]; i2 = e; }

            float wn = 1.0f / (v1 + v2);
            int s1 = atomicAdd(&G_COUNTS[i1], 1);
            g_tokidx[i1 * CAP + s1] = tok;  g_tokw[i1 * CAP + s1] = v1 * wn;
            int s2 = atomicAdd(&G_COUNTS[i2], 1);
            g_tokidx[i2 * CAP + s2] = tok;  g_tokw[i2 * CAP + s2] = v2 * wn;
        }
    } else {
        size_t total = n8x + n8w;
        size_t nConvBlocks = gridDim.x - nRouterBlocks;
        size_t i = (size_t)(blockIdx.x - nRouterBlocks) * blockDim.x + threadIdx.x;
        size_t stride = nConvBlocks * blockDim.x;
        for (; i < total; i += stride) {
            if (i < n8w) conv8(w1, g_w1h, i);
            else         conv8(x,  g_xh,  i - n8w);
        }
    }
}

// ---------------- FFN1 (+ aux + w2 conversion slab at z==0) ----------------
// Grid z: 0 = conversion slab (lowest block ids -> wave 1), 1..NE = experts (e = z-1).
__global__ __launch_bounds__(256, 2)
void ffn1_kernel(const float* __restrict__ b1, const float* __restrict__ w2,
                 float* out_aux, float invT, size_t n8w2) {
    extern __shared__ unsigned smem[];
    int* s_tok = (int*)smem;

    if (blockIdx.z == 0) {
        // aux loss (router done; write once)
        if (blockIdx.x == 0 && blockIdx.y == 0 && threadIdx.x == 0 && out_aux != nullptr) {
            float m[NE]; float mu = 0.0f;
#pragma unroll
            for (int e = 0; e < NE; e++) { m[e] = G_SUMPROBS[e] * invT; mu += m[e]; }
            mu *= (1.0f / NE);
            float v = 0.0f;
#pragma unroll
            for (int e = 0; e < NE; e++) { float d = m[e] - mu; v += d * d; }
            *out_aux = v / (NE - 1);
        }
        // w2 fp16 conversion, grid-stride over the z==0 slab
        size_t i = (size_t)(blockIdx.y * gridDim.x + blockIdx.x) * blockDim.x + threadIdx.x;
        size_t stride = (size_t)gridDim.x * gridDim.y * blockDim.x;
        for (; i < n8w2; i += stride) conv8(w2, g_w2h, i);
        return;
    }

    int e = blockIdx.z - 1;
    int count = G_COUNTS[e];
    int row0 = blockIdx.y * 128;
    if (row0 >= count) return;
    int col0 = blockIdx.x * 128;

    int t = threadIdx.x;
    if (t < 128) {
        int gr = row0 + t;
        s_tok[t] = g_tokidx[e * CAP + (gr < count ? gr : count - 1)];
    }
    __syncthreads();

    int lane = t & 31, wid = t >> 5;
    int warp_m = wid >> 2, warp_n = wid & 3;
    int gid = lane >> 2, tig = lane & 3;
    int lrow = (lane & 7) + (lane & 8);
    int lk   = ((lane >> 4) & 1) * 8;

    uint32_t sb = smem_u32(smem);

    const unsigned* aS[4]; uint32_t aD[4];
    const unsigned* bS[4]; uint32_t bD[4];
    const unsigned* w1e = g_w1h + (size_t)e * (D_MODEL * D_FF / 2) + col0 / 2;
#pragma unroll
    for (int i = 0; i < 4; i++) {
        int cid = t + 256 * i;
        int arow = cid >> 3, ach = cid & 7;
        aS[i] = g_xh + (size_t)s_tok[arow] * (D_MODEL / 2) + ach * 4;
        aD[i] = sb + OFFA(0) + arow * APITCH + ach * 16;
        int brow = cid >> 4, bch = cid & 15;
        bS[i] = w1e + (size_t)brow * (D_FF / 2) + bch * 4;
        bD[i] = sb + OFFB(0) + brow * BPITCH + bch * 16;
    }

    float acc[4][4][4];
#pragma unroll
    for (int i = 0; i < 4; i++)
#pragma unroll
        for (int j = 0; j < 4; j++)
#pragma unroll
            for (int q = 0; q < 4; q++) acc[i][j][q] = 0.0f;

#pragma unroll
    for (int i = 0; i < 4; i++) { cp16(aD[i], aS[i]); cp16(bD[i], bS[i]); }
    CP_COMMIT();

    const int NIT = D_MODEL / BK;   // 16
    int buf = 0;
    for (int it = 0; it < NIT; it++) {
        CP_WAIT0();
        __syncthreads();
        if (it + 1 < NIT) {
            int ktw = (it + 1) * (BK / 2);
            uint32_t as = (buf ^ 1) * ABYTES;
            uint32_t bs = (buf ^ 1) * BBYTES;
#pragma unroll
            for (int i = 0; i < 4; i++) {
                cp16(aD[i] + as, aS[i] + ktw);
                cp16(bD[i] + bs, bS[i] + (size_t)(it + 1) * BK * (D_FF / 2));
            }
            CP_COMMIT();
        }

        uint32_t sbA = sb + OFFA(buf);
        uint32_t sbB = sb + OFFB(buf);
#pragma unroll
        for (int ks = 0; ks < BK; ks += 16) {
            unsigned af[4][4], bf[4][2];
#pragma unroll
            for (int i = 0; i < 4; i++) {
                int m = warp_m * 64 + i * 16;
                uint32_t ad = sbA + (m + lrow) * APITCH + (ks + lk) * 2;
                LDMX4(af[i][0], af[i][1], af[i][2], af[i][3], ad);
            }
#pragma unroll
            for (int jj = 0; jj < 2; jj++) {
                uint32_t bd = sbB + (ks + lrow) * BPITCH
                            + (warp_n * 32 + jj * 16 + lk) * 2;
                LDMX4T(bf[jj*2][0], bf[jj*2][1], bf[jj*2+1][0], bf[jj*2+1][1], bd);
            }
#pragma unroll
            for (int i = 0; i < 4; i++)
#pragma unroll
                for (int j = 0; j < 4; j++)
                    mma_f16(acc[i][j], af[i][0], af[i][1], af[i][2], af[i][3],
                            bf[j][0], bf[j][1]);
        }
        buf ^= 1;
    }

#pragma unroll
    for (int i = 0; i < 4; i++) {
        int mrow = warp_m * 64 + i * 16 + gid;
#pragma unroll
        for (int half = 0; half < 2; half++) {
            int gr = row0 + mrow + half * 8;
            if (gr >= count) continue;
            unsigned* hrow = g_hh + ((size_t)e * CAP + gr) * (D_FF / 2) + col0 / 2;
#pragma unroll
            for (int j = 0; j < 4; j++) {
                int c = warp_n * 32 + j * 8 + tig * 2;
                float v0 = acc[i][j][half * 2 + 0] + b1[e * D_FF + col0 + c];
                float v1 = acc[i][j][half * 2 + 1] + b1[e * D_FF + col0 + c + 1];
                float g0 = 0.5f * v0 * (1.0f + erff(v0 * 0.70710678118654752f));
                float g1 = 0.5f * v1 * (1.0f + erff(v1 * 0.70710678118654752f));
                hrow[c / 2] = pack_h2(g0, g1);
            }
        }
    }
}

// ---------------- FFN2: out += w * (h @ w2[e] + b2[e]) ----------------
__global__ __launch_bounds__(256, 2)
void ffn2_kernel(const float* __restrict__ b2, float* __restrict__ out) {
    extern __shared__ unsigned smem[];
    int*   s_tok = (int*)smem;
    float* s_w   = (float*)(smem + 128);

    int e = blockIdx.z;
    int count = G_COUNTS[e];
    int row0 = blockIdx.y * 128;
    if (row0 >= count) return;
    int col0 = blockIdx.x * 128;

    int t = threadIdx.x;
    if (t < 128) {
        int gr = row0 + t;
        int idx = gr < count ? gr : count - 1;
        s_tok[t] = g_tokidx[e * CAP + idx];
        s_w[t]   = (gr < count) ? g_tokw[e * CAP + idx] : 0.0f;
    }
    __syncthreads();

    int lane = t & 31, wid = t >> 5;
    int warp_m = wid >> 2, warp_n = wid & 3;
    int gid = lane >> 2, tig = lane & 3;
    int lrow = (lane & 7) + (lane & 8);
    int lk   = ((lane >> 4) & 1) * 8;

    uint32_t sb = smem_u32(smem);

    const unsigned* he  = g_hh + ((size_t)e * CAP + row0) * (D_FF / 2);
    const unsigned* w2e = g_w2h + (size_t)e * (D_FF * D_MODEL / 2) + col0 / 2;

    const unsigned* aS[4]; uint32_t aD[4];
    const unsigned* bS[4]; uint32_t bD[4];
#pragma unroll
    for (int i = 0; i < 4; i++) {
        int cid = t + 256 * i;
        int arow = cid >> 3, ach = cid & 7;
        aS[i] = he + (size_t)arow * (D_FF / 2) + ach * 4;
        aD[i] = sb + OFFA(0) + arow * APITCH + ach * 16;
        int brow = cid >> 4, bch = cid & 15;
        bS[i] = w2e + (size_t)brow * (D_MODEL / 2) + bch * 4;
        bD[i] = sb + OFFB(0) + brow * BPITCH + bch * 16;
    }

    float acc[4][4][4];
#pragma unroll
    for (int i = 0; i < 4; i++)
#pragma unroll
        for (int j = 0; j < 4; j++)
#pragma unroll
            for (int q = 0; q < 4; q++) acc[i][j][q] = 0.0f;

#pragma unroll
    for (int i = 0; i < 4; i++) { cp16(aD[i], aS[i]); cp16(bD[i], bS[i]); }
    CP_COMMIT();

    const int NIT = D_FF / BK;   // 64
    int buf = 0;
    for (int it = 0; it < NIT; it++) {
        CP_WAIT0();
        __syncthreads();
        if (it + 1 < NIT) {
            int ktw = (it + 1) * (BK / 2);
            uint32_t as = (buf ^ 1) * ABYTES;
            uint32_t bs = (buf ^ 1) * BBYTES;
#pragma unroll
            for (int i = 0; i < 4; i++) {
                cp16(aD[i] + as, aS[i] + ktw);
                cp16(bD[i] + bs, bS[i] + (size_t)(it + 1) * BK * (D_MODEL / 2));
            }
            CP_COMMIT();
        }

        uint32_t sbA = sb + OFFA(buf);
        uint32_t sbB = sb + OFFB(buf);
#pragma unroll
        for (int ks = 0; ks < BK; ks += 16) {
            unsigned af[4][4], bf[4][2];
#pragma unroll
            for (int i = 0; i < 4; i++) {
                int m = warp_m * 64 + i * 16;
                uint32_t ad = sbA + (m + lrow) * APITCH + (ks + lk) * 2;
                LDMX4(af[i][0], af[i][1], af[i][2], af[i][3], ad);
            }
#pragma unroll
            for (int jj = 0; jj < 2; jj++) {
                uint32_t bd = sbB + (ks + lrow) * BPITCH
                            + (warp_n * 32 + jj * 16 + lk) * 2;
                LDMX4T(bf[jj*2][0], bf[jj*2][1], bf[jj*2+1][0], bf[jj*2+1][1], bd);
            }
#pragma unroll
            for (int i = 0; i < 4; i++)
#pragma unroll
                for (int j = 0; j < 4; j++)
                    mma_f16(acc[i][j], af[i][0], af[i][1], af[i][2], af[i][3],
                            bf[j][0], bf[j][1]);
        }
        buf ^= 1;
    }

#pragma unroll
    for (int i = 0; i < 4; i++) {
        int mrow = warp_m * 64 + i * 16 + gid;
#pragma unroll
        for (int half = 0; half < 2; half++) {
            int r = mrow + half * 8;
            int gr = row0 + r;
            if (gr >= count) continue;
            int tok = s_tok[r];
            float w  = s_w[r];
            float* orow = out + (size_t)tok * D_MODEL + col0;
#pragma unroll
            for (int j = 0; j < 4; j++) {
                int c = warp_n * 32 + j * 8 + tig * 2;
                float v0 = acc[i][j][half * 2 + 0] + b2[e * D_MODEL + col0 + c];
                float v1 = acc[i][j][half * 2 + 1] + b2[e * D_MODEL + col0 + c + 1];
                atomicAdd(&orow[c],     w * v0);
                atomicAdd(&orow[c + 1], w * v1);
            }
        }
    }
}

// ---------------- launch ----------------
extern "C" void kernel_launch(void* const* d_in, const int* in_sizes, int n_in,
                              void* d_out, int out_size) {
    const float* x  = (const float*)d_in[0];
    const float* rw = (const float*)d_in[1];
    const float* rb = (const float*)d_in[2];
    const float* w1 = (const float*)d_in[3];
    const float* b1 = (const float*)d_in[4];
    const float* w2 = (const float*)d_in[5];
    const float* b2 = (const float*)d_in[6];
    float* out = (float*)d_out;

    int T = in_sizes[0] / D_MODEL;

    cudaFuncSetAttribute(ffn1_kernel, cudaFuncAttributeMaxDynamicSharedMemorySize, DYN_BYTES);
    cudaFuncSetAttribute(ffn2_kernel, cudaFuncAttributeMaxDynamicSharedMemorySize, DYN_BYTES);

    // 1) zero control block
    void* ctrlp = nullptr;
    cudaGetSymbolAddress(&ctrlp, g_ctrl);
    cudaMemsetAsync(ctrlp, 0, 64);

    // 2) router + conversion of w1|x
    int nRouterBlocks = (T + 7) / 8;
    conv_router_kernel<<<nRouterBlocks + 4096, 256>>>(
        x, rw, rb, w1, out, T, nRouterBlocks,
        (size_t)T * D_MODEL / 8, (size_t)NE * D_MODEL * D_FF / 8);

    // 3) ffn1 (+ aux, + w2 conversion slab at z==0)
    float* aux_ptr = (out_size > T * D_MODEL) ? (out + (size_t)T * D_MODEL) : nullptr;
    dim3 g1(D_FF / 128, CAP / 128, NE + 1);
    ffn1_kernel<<<g1, 256, DYN_BYTES>>>(b1, w2, aux_ptr, 1.0f / (float)T,
                                        (size_t)NE * D_FF * D_MODEL / 8);

    // 4) ffn2
    dim3 g2(D_MODEL / 128, CAP / 128, NE);
    ffn2_kernel<<<g2, 256, DYN_BYTES>>>(b2, out);
}